// round 16
// baseline (speedup 1.0000x reference)
#include <cuda_runtime.h>
#include <cstdint>

#define NQ     4
#define IMG    576
#define TPB    256
#define SPR    4                 // samples per round
#define NBUF   4                 // ring depth
#define SS     584               // padded sample stride in smem floats
#define BUFB   (SPR * SS * 4)    // bytes per stage buffer
#define NBLK   592               // 148 SMs x 4 blocks
#define BN_EPS 1e-5f

// static scratch (no allocation); double-buffered sums selected by replay epoch
__device__ float g_sums[2][8] = {{0.f}};
__device__ unsigned int g_t1 = 0;   // k_main epoch ticket (monotonic)
__device__ unsigned int g_t2 = 0;   // k_finish epoch ticket (monotonic)

__device__ __forceinline__ void cp_async16(uint32_t smem_addr, const void* gptr) {
    asm volatile("cp.async.cg.shared.global [%0], [%1], 16;\n" :: "r"(smem_addr), "l"(gptr));
}
#define CP_COMMIT() asm volatile("cp.async.commit_group;\n" ::: "memory")
#define CP_WAIT2()  asm volatile("cp.async.wait_group 2;\n" ::: "memory")

__device__ __forceinline__ uint32_t stage_off(int i4) {
    int s = i4 / 144, w = i4 - s * 144;
    return (uint32_t)(s * SS + w * 4) * 4u;
}

// ---------------- fused pool + circuit + atomic stats (R7 core) ----------------
__global__ void __launch_bounds__(TPB, 4) k_main(
    const float* __restrict__ x,
    const float* __restrict__ enc_w,   // (4,16)
    const float* __restrict__ enc_b,   // (4,)
    const float* __restrict__ qp,      // (2,4)
    float* __restrict__ zout,          // (B,4)
    int R_total)
{
    __shared__ float stage[NBUF][SPR * SS];   // 4 x 9344 B
    __shared__ float pr[NBUF][SPR][17];
    __shared__ float sred[8][8];
    __shared__ unsigned int s_par;

    const int t    = threadIdx.x;
    const int blk  = blockIdx.x;
    const int nblk = gridDim.x;

    const int r0 = (int)((long long)blk * R_total / nblk);
    const int r1 = (int)((long long)(blk + 1) * R_total / nblk);
    const int n  = r1 - r0;                       // ~55-56

    const float4* xg = (const float4*)(x + (size_t)r0 * SPR * IMG);
    const uint32_t sb = (uint32_t)__cvta_generic_to_shared(&stage[0][0]);

    // round-invariant staging offsets (576 float4 per round)
    const int i4a = t, i4b = t + 256;
    const uint32_t offa = stage_off(i4a);
    const uint32_t offb = stage_off(i4b);
    const bool hasC = (t < 64);
    const uint32_t offc = hasC ? stage_off(t + 512) : 0u;

    float enc[NQ];
#pragma unroll
    for (int k = 0; k < NQ; k++) enc[k] = __ldg(enc_b + k);

    // prologue: issue rounds 0..2
#pragma unroll
    for (int j = 0; j < 3; j++) {
        if (j < n) {
            const float4* src = xg + (size_t)j * 576;
            uint32_t base = sb + (uint32_t)(j & 3) * BUFB;
            cp_async16(base + offa, src + i4a);
            cp_async16(base + offb, src + i4b);
            if (hasC) cp_async16(base + offc, src + (t + 512));
        }
        CP_COMMIT();
    }

#pragma unroll 1
    for (int r = 0; r < n; r++) {
        CP_WAIT2();
        __syncthreads();

        // refill round r+3 into freed buffer
        if (r + 3 < n) {
            const float4* src = xg + (size_t)(r + 3) * 576;
            uint32_t base = sb + (uint32_t)((r + 3) & 3) * BUFB;
            cp_async16(base + offa, src + i4a);
            cp_async16(base + offb, src + i4b);
            if (hasC) cp_async16(base + offc, src + (t + 512));
        }
        CP_COMMIT();

        // pool round r: rotating 2-warp duty
        {
            int tp = t - ((r & 3) << 6);
            if ((unsigned)tp < 64u) {
                int s  = tp >> 4, b = tp & 15;
                int rb = b >> 2, cb = b & 3;
                const float* bp = &stage[r & 3][0] + s * SS + rb * 144 + cb * 6;
                float acc = 0.f;
#pragma unroll
                for (int dr = 0; dr < 6; dr++) {
                    const float2* p2 = (const float2*)(bp + dr * 24);
                    float2 a = p2[0], c = p2[1], d = p2[2];
                    acc += (a.x + a.y) + (c.x + c.y) + (d.x + d.y);
                }
                pr[r & 3][s][b] = acc * (1.0f / 36.0f);
            }
        }

        // owners of round r-1 fold pooled -> enc
        if (r > 0 && (t >> 2) == r - 1) {
            const float* pv = pr[(r - 1) & 3][t & 3];
#pragma unroll
            for (int k = 0; k < NQ; k++) {
                float a = enc[k];
#pragma unroll
                for (int i = 0; i < 16; i++)
                    a += pv[i] * __ldg(enc_w + k * 16 + i);
                enc[k] = a;
            }
        }
    }

    // drain: fold last round
    __syncthreads();
    if ((t >> 2) == n - 1) {
        const float* pv = pr[(n - 1) & 3][t & 3];
#pragma unroll
        for (int k = 0; k < NQ; k++) {
            float a = enc[k];
#pragma unroll
            for (int i = 0; i < 16; i++)
                a += pv[i] * __ldg(enc_w + k * 16 + i);
            enc[k] = a;
        }
    }

    const bool active = t < 4 * n;

    // ---- statevector circuit in registers ----
    float sx[16], sy[16];
#pragma unroll
    for (int i = 0; i < 16; i++) { sx[i] = 0.f; sy[i] = 0.f; }
    sx[0] = 1.f;

#pragma unroll
    for (int layer = 0; layer < 2; layer++) {
#pragma unroll
        for (int q = 0; q < NQ; q++) {
            const int st = 8 >> q;
            float c, sn;
            __sincosf(0.5f * enc[q], &sn, &c);
#pragma unroll
            for (int i = 0; i < 16; i++) {
                if ((i & st) == 0) {
                    const int j = i | st;
                    float ax = sx[i], ay = sy[i];
                    float bx = sx[j], by = sy[j];
                    sx[i] = c * ax - sn * bx;  sy[i] = c * ay - sn * by;
                    sx[j] = sn * ax + c * bx;  sy[j] = sn * ay + c * by;
                }
            }
            float hc, hs;
            __sincosf(0.5f * __ldg(qp + layer * NQ + q), &hs, &hc);
#pragma unroll
            for (int i = 0; i < 16; i++) {
                float xx = sx[i], yy = sy[i];
                if (i & st) { sx[i] = xx * hc - yy * hs;  sy[i] = yy * hc + xx * hs; }
                else        { sx[i] = xx * hc + yy * hs;  sy[i] = yy * hc - xx * hs; }
            }
        }
        {   // composed CNOT ring permutation
            constexpr int P[16] = {0, 13, 3, 14, 6, 11, 5, 8, 12, 1, 15, 2, 10, 7, 9, 4};
            float tx[16], ty[16];
#pragma unroll
            for (int i = 0; i < 16; i++) { tx[i] = sx[i]; ty[i] = sy[i]; }
#pragma unroll
            for (int i = 0; i < 16; i++) { sx[i] = tx[P[i]]; sy[i] = ty[P[i]]; }
        }
    }

    // ---- Z expectations (masked) + store raw z ----
    float z0 = 0.f, z1 = 0.f, z2 = 0.f, z3 = 0.f;
    if (active) {
#pragma unroll
        for (int i = 0; i < 16; i++) {
            float p2 = sx[i] * sx[i] + sy[i] * sy[i];
            z0 += ((i >> 3) & 1) ? -p2 : p2;
            z1 += ((i >> 2) & 1) ? -p2 : p2;
            z2 += ((i >> 1) & 1) ? -p2 : p2;
            z3 += ( i       & 1) ? -p2 : p2;
        }
        *(float4*)(zout + ((size_t)r0 * SPR + t) * 4) = make_float4(z0, z1, z2, z3);
    }

    // ---- deterministic block reduce, then fire-and-forget atomic sums ----
    float v[8] = {z0, z1, z2, z3, z0 * z0, z1 * z1, z2 * z2, z3 * z3};
#pragma unroll
    for (int off = 16; off >= 1; off >>= 1)
#pragma unroll
        for (int j = 0; j < 8; j++)
            v[j] += __shfl_xor_sync(0xffffffffu, v[j], off);

    const int wid = t >> 5, lid = t & 31;
    if (lid == 0)
#pragma unroll
        for (int j = 0; j < 8; j++) sred[wid][j] = v[j];
    if (t == 0) {
        unsigned int e = atomicAdd(&g_t1, 1u) / (unsigned)nblk;   // replay epoch
        s_par = e & 1u;
    }
    __syncthreads();
    if (t < 8) {
        float a = 0.f;
#pragma unroll
        for (int w = 0; w < 8; w++) a += sred[w][t];
        atomicAdd(&g_sums[s_par][t], a);
    }
}

// ---------------- k_finish: barrier-free scale/shift + normalize ----------------
__global__ void __launch_bounds__(256) k_finish(
    const float* __restrict__ bnw,
    const float* __restrict__ bnb,
    float* __restrict__ zout,
    int B)
{
    __shared__ unsigned int s_par;
    const int t = threadIdx.x;

    if (t == 0) {
        unsigned int e = atomicAdd(&g_t2, 1u) / gridDim.x;   // same replay epoch
        s_par = e & 1u;
    }
    __syncthreads();
    const unsigned int p = s_par;

    // broadcast-load the 8 sums; per-thread scale/shift (redundant, no barriers)
    const float* sums = &g_sums[p][0];
    float s0 = sums[0], s1 = sums[1], s2 = sums[2], s3 = sums[3];
    float q0 = sums[4], q1 = sums[5], q2 = sums[6], q3 = sums[7];

    const float invB = 1.0f / (float)B;
    float m0 = s0 * invB, m1 = s1 * invB, m2 = s2 * invB, m3 = s3 * invB;
    float sc0 = rsqrtf(q0 * invB - m0 * m0 + BN_EPS) * __ldg(bnw + 0);
    float sc1 = rsqrtf(q1 * invB - m1 * m1 + BN_EPS) * __ldg(bnw + 1);
    float sc2 = rsqrtf(q2 * invB - m2 * m2 + BN_EPS) * __ldg(bnw + 2);
    float sc3 = rsqrtf(q3 * invB - m3 * m3 + BN_EPS) * __ldg(bnw + 3);
    float sh0 = __ldg(bnb + 0) - m0 * sc0;
    float sh1 = __ldg(bnb + 1) - m1 * sc1;
    float sh2 = __ldg(bnb + 2) - m2 * sc2;
    float sh3 = __ldg(bnb + 3) - m3 * sc3;

    // one float4 per thread
    const int i = blockIdx.x * 256 + t;
    if (i < B) {
        float4 z = ((float4*)zout)[i];
        z.x = z.x * sc0 + sh0;
        z.y = z.y * sc1 + sh1;
        z.z = z.z * sc2 + sh2;
        z.w = z.w * sc3 + sh3;
        ((float4*)zout)[i] = z;
    }

    // zero the other buffer for the next replay (benign redundant writes)
    if (t < 8) g_sums[p ^ 1u][t] = 0.f;
}

extern "C" void kernel_launch(void* const* d_in, const int* in_sizes, int n_in,
                              void* d_out, int out_size)
{
    const float* x     = (const float*)d_in[0];
    const float* enc_w = (const float*)d_in[1];
    const float* enc_b = (const float*)d_in[2];
    const float* qp    = (const float*)d_in[3];
    const float* bnw   = (const float*)d_in[4];
    const float* bnb   = (const float*)d_in[5];
    float* out = (float*)d_out;

    int B       = in_sizes[0] / IMG;   // 131072
    int R_total = B / SPR;             // 32768

    k_main<<<NBLK, TPB>>>(x, enc_w, enc_b, qp, out, R_total);
    k_finish<<<(B + 255) / 256, 256>>>(bnw, bnb, out, B);
}